// round 16
// baseline (speedup 1.0000x reference)
#include <cuda_runtime.h>
#include <cuda_bf16.h>
#include <math.h>

#define BB   64
#define TT   512
#define IND  256
#define HH   1024
#define OUTD 256

#define NCTA 64
#define COLS 16
#define RSTR 76

// -------- device scratch --------
__device__ float g_xh[TT * BB * HH];      // [t][j][b]
__device__ float g_xz[TT * BB * HH];
__device__ float g_xr[TT * BB * HH];
__device__ unsigned g_hB[2][32768];       // h  bf16x2-packed A-frags, double-buffered
__device__ float g_hrP[2][HH * BB];       // h*r tf32 fragment-packed, double-buffered
__device__ float g_hT [HH * BB];          // plain [j][b], final step only
__device__ unsigned g_fh [NCTA];
__device__ unsigned g_fhr[NCTA];

// -------- helpers --------
__device__ __forceinline__ unsigned cvt_tf32(float x) {
    unsigned r; asm("cvt.rna.tf32.f32 %0, %1;" : "=r"(r) : "f"(x)); return r;
}
__device__ __forceinline__ unsigned bf16pack(float hi, float lo) {
    unsigned r; asm("cvt.rn.bf16x2.f32 %0, %1, %2;" : "=r"(r) : "f"(hi), "f"(lo)); return r;
}
__device__ __forceinline__ void mma8(float (&d)[4], const unsigned (&a)[4], const unsigned (&b)[2]) {
    asm volatile("mma.sync.aligned.m16n8k8.row.col.f32.tf32.tf32.f32 "
                 "{%0,%1,%2,%3}, {%4,%5,%6,%7}, {%8,%9}, {%0,%1,%2,%3};"
                 : "+f"(d[0]), "+f"(d[1]), "+f"(d[2]), "+f"(d[3])
                 : "r"(a[0]), "r"(a[1]), "r"(a[2]), "r"(a[3]), "r"(b[0]), "r"(b[1]));
}
__device__ __forceinline__ void mma16(float (&d)[4], const unsigned (&a)[4], const unsigned (&b)[2]) {
    asm volatile("mma.sync.aligned.m16n8k16.row.col.f32.bf16.bf16.f32 "
                 "{%0,%1,%2,%3}, {%4,%5,%6,%7}, {%8,%9}, {%0,%1,%2,%3};"
                 : "+f"(d[0]), "+f"(d[1]), "+f"(d[2]), "+f"(d[3])
                 : "r"(a[0]), "r"(a[1]), "r"(a[2]), "r"(a[3]), "r"(b[0]), "r"(b[1]));
}
__device__ __forceinline__ float sigm_(float x) { return 1.0f / (1.0f + __expf(-x)); }

__device__ __forceinline__ unsigned long long splat2(float x) {
    unsigned long long r; asm("mov.b64 %0, {%1, %1};" : "=l"(r) : "f"(x)); return r;
}
__device__ __forceinline__ unsigned long long pack2(float x, float y) {
    unsigned long long r; asm("mov.b64 %0, {%1, %2};" : "=l"(r) : "f"(x), "f"(y)); return r;
}
__device__ __forceinline__ void fma2(unsigned long long& d, unsigned long long a, unsigned long long b) {
    asm("fma.rn.f32x2 %0, %1, %2, %0;" : "+l"(d) : "l"(a), "l"(b));
}
__device__ __forceinline__ float2 unpack2(unsigned long long v) {
    float2 f; asm("mov.b64 {%0, %1}, %2;" : "=f"(f.x), "=f"(f.y) : "l"(v)); return f;
}

// -------- dataflow sync --------
__device__ __forceinline__ void publish(unsigned* flag, unsigned val) {
    asm volatile("st.release.gpu.global.u32 [%0], %1;" :: "l"(flag), "r"(val) : "memory");
}
// Warp-collective wait on 8 producer CTAs (lanes poll flags[base + (lane&7)]).
__device__ __forceinline__ void wait8(const unsigned* flags, int base, unsigned target) {
    const unsigned* p = flags + base + (threadIdx.x & 7);
    unsigned v;
    do {
        asm volatile("ld.acquire.gpu.global.u32 %0, [%1];" : "=r"(v) : "l"(p) : "memory");
    } while (!__all_sync(0xffffffffu, (int)(v - target) >= 0));
}

// -------- kernel 1: input projections --------
__global__ __launch_bounds__(256) void proj_kernel(
    const float* __restrict__ X,
    const float* __restrict__ W0, const float* __restrict__ W1, const float* __restrict__ W2,
    const float* __restrict__ b0, const float* __restrict__ b1, const float* __restrict__ b2)
{
    __shared__ float As[32][68];
    __shared__ float Bs[32][68];

    const int z = blockIdx.z;
    const float* W    = (z == 0) ? W0 : (z == 1) ? W1 : W2;
    const float* bias = (z == 0) ? b0 : (z == 1) ? b1 : b2;
    float*       outp = (z == 0) ? g_xh : (z == 1) ? g_xz : g_xr;

    const int t   = blockIdx.y;
    const int j0  = blockIdx.x * 64;
    const int tid = threadIdx.x;
    const int ty  = tid >> 4;
    const int tx  = tid & 15;

    unsigned long long acc2[4][2];
#pragma unroll
    for (int i = 0; i < 4; i++) { acc2[i][0] = 0ull; acc2[i][1] = 0ull; }

    for (int kt = 0; kt < IND; kt += 32) {
#pragma unroll
        for (int l = 0; l < 8; l++) {
            int flat = tid + l * 256;
            int row = flat >> 5, col = flat & 31;
            As[col][row] = W[(j0 + row) * IND + kt + col];
            Bs[col][row] = X[row * (TT * IND) + t * IND + kt + col];
        }
        __syncthreads();
#pragma unroll
        for (int kk = 0; kk < 32; kk++) {
            float4 a4 = *reinterpret_cast<const float4*>(&As[kk][ty * 4]);
            float4 b4 = *reinterpret_cast<const float4*>(&Bs[kk][tx * 4]);
            unsigned long long p01 = pack2(b4.x, b4.y);
            unsigned long long p23 = pack2(b4.z, b4.w);
            float a[4] = { a4.x, a4.y, a4.z, a4.w };
#pragma unroll
            for (int i = 0; i < 4; i++) {
                unsigned long long aa = splat2(a[i]);
                fma2(acc2[i][0], aa, p01);
                fma2(acc2[i][1], aa, p23);
            }
        }
        __syncthreads();
    }
#pragma unroll
    for (int i = 0; i < 4; i++) {
        int j = j0 + ty * 4 + i;
        float bvv = bias[j];
        float2 p0 = unpack2(acc2[i][0]);
        float2 p1 = unpack2(acc2[i][1]);
        float4 v = make_float4(p0.x + bvv, p0.y + bvv, p1.x + bvv, p1.y + bvv);
        *reinterpret_cast<float4*>(&outp[t * (HH * BB) + j * BB + tx * 4]) = v;
    }
}

// -------- cross-warp reduction (R8 verbatim) --------
__device__ __forceinline__ void reduce16(float* red, const float (*a)[2][4],
                                         int w, int c, int q, int jj, int b0, float (&s)[4])
{
    if (w < 4) {
#pragma unroll
        for (int mt = 0; mt < 4; mt++)
#pragma unroll
            for (int nt = 0; nt < 2; nt++) {
                float* p = &red[(w * 16 + nt * 8 + 2 * c) * RSTR + mt * 16 + q];
                p[0] = a[mt][nt][0]; p[RSTR] = a[mt][nt][1];
                p[8] = a[mt][nt][2]; p[RSTR + 8] = a[mt][nt][3];
            }
    }
    __syncthreads();
    if (w >= 4) {
#pragma unroll
        for (int mt = 0; mt < 4; mt++)
#pragma unroll
            for (int nt = 0; nt < 2; nt++) {
                float* p = &red[((w - 4) * 16 + nt * 8 + 2 * c) * RSTR + mt * 16 + q];
                p[0] += a[mt][nt][0]; p[RSTR] += a[mt][nt][1];
                p[8] += a[mt][nt][2]; p[RSTR + 8] += a[mt][nt][3];
            }
    }
    __syncthreads();
    s[0] = s[1] = s[2] = s[3] = 0.f;
#pragma unroll
    for (int p4 = 0; p4 < 4; p4++) {
        float4 v = *(const float4*)&red[(p4 * 16 + jj) * RSTR + b0];
        s[0] += v.x; s[1] += v.y; s[2] += v.z; s[3] += v.w;
    }
}

// -------- kernel 2: persistent scan --------
// Phase 1: tf32 k8 (hr, precision path). Phase 2: bf16 k16 (gates, 2x MAC/instr).
__global__ __launch_bounds__(256, 1) void scan_kernel(
    const float* __restrict__ Wh, const float* __restrict__ Vz, const float* __restrict__ Vr)
{
    extern __shared__ float smem[];
    float*    Bp   = smem;                           // Wh tf32 frags: 16384 floats
    unsigned* Bz16 = (unsigned*)(smem + 16384);      // Vz bf16 frags: 8192 u32
    unsigned* Br16 = (unsigned*)(smem + 24576);      // Vr bf16 frags: 8192 u32
    float*    red  = smem + 32768;                   // 4*16*RSTR floats

    const int tid  = threadIdx.x;
    const int w    = tid >> 5;
    const int lane = tid & 31;
    const int j0   = blockIdx.x * COLS;

    const unsigned F0h  = g_fh [blockIdx.x];
    const unsigned F0hr = g_fhr[blockIdx.x];

    // Wh tf32 fragments (R8 packing, g=0 slice)
    for (int idx = tid; idx < COLS * HH; idx += 256) {
        int j = idx >> 10, k = idx & 1023;
        float v = Wh[(j0 + j) * HH + k];
        int ksg = k >> 3, kk = k & 7;
        Bp[((ksg * 2 + (j >> 3)) * 64) + ((j & 7) * 4 + (kk & 3)) * 2 + (kk >> 2)]
            = __uint_as_float(cvt_tf32(v));
    }
    // Vz/Vr bf16 fragments: slot((kc*2+nt)*32 + q*4+c)*2 + i  holds V[n][k],V[n][k+1]
    // with n = nt*8+q, k = kc*16 + 2c + 8i
    for (int idx = tid; idx < COLS * (HH / 2); idx += 256) {
        int k2 = idx & 511, jl = idx >> 9;
        int k = 2 * k2;
        int kc = k2 >> 3, k2o = k2 & 7;
        int cc = k2o & 3, ii = k2o >> 2;
        int qq = jl & 7, nt = jl >> 3;
        int ad = ((kc * 2 + nt) * 32 + qq * 4 + cc) * 2 + ii;
        const float* Vz_r = &Vz[(j0 + jl) * HH + k];
        const float* Vr_r = &Vr[(j0 + jl) * HH + k];
        Bz16[ad] = bf16pack(Vz_r[1], Vz_r[0]);
        Br16[ad] = bf16pack(Vr_r[1], Vr_r[0]);
    }

    const int jj = tid >> 4;
    const int b0 = (tid & 15) * 4;
    const int kj = j0 + jj;
    const int pkk = kj & 7;
    const int pbi = b0 & 15;
    const int pbase = (((kj >> 7) * 4 + (b0 >> 4)) * 16 + ((kj >> 3) & 15)) * 128
                    + ((pbi & 7) * 4 + (pkk & 3)) * 4 + ((pbi >> 3) + 2 * (pkk >> 2));

    // bf16 h store addressing (even-jj threads store pairs (jj, jj+1))
    const int cc_h = (jj >> 1) & 3;
    const int nt_h = jj >> 3;
    const int mt_h = b0 >> 4;
    const int p_h  = (b0 >> 3) & 1;
    const int q0_h = b0 & 7;
    const int hb_base = ((blockIdx.x * 4 + mt_h) * 32 + q0_h * 4 + cc_h) * 4 + p_h + 2 * nt_h;

    float hst[4] = {0, 0, 0, 0}, zst[4] = {0, 0, 0, 0};

    // hr@-1 = 0 into buffer 1, publish
#pragma unroll
    for (int i = 0; i < 4; i++) __stcg(&g_hrP[1][pbase + i * 16], 0.0f);
    __syncthreads();
    if (tid == 0) publish(&g_fhr[blockIdx.x], F0hr + 1);

    const int c = lane & 3, q = lane >> 2;
    const int Abase = lane * 4;
    const int prodbase = w * 8;      // 8 producer CTAs of this warp's K=128

    for (int t = 0; t < TT; t++) {
        const int xo = t * (HH * BB) + kj * BB + b0;
        float4 xh4 = *(const float4*)&g_xh[xo];
        float4 xz4 = *(const float4*)&g_xz[xo];
        float4 xr4 = *(const float4*)&g_xr[xo];

        // ---------- phase 1: (h*r) @ Wh^T  (tf32 k8) ----------
        wait8(g_fhr, prodbase, F0hr + 1 + t);
        const float* hrbuf = g_hrP[(t + 1) & 1];

        float acc[4][2][4];
#pragma unroll
        for (int mt = 0; mt < 4; mt++)
#pragma unroll
            for (int nt = 0; nt < 2; nt++)
#pragma unroll
                for (int r = 0; r < 4; r++) acc[mt][nt][r] = 0.f;

#pragma unroll 4
        for (int ks = 0; ks < 16; ks++) {
            int kg = w * 16 + ks;
            float2 f0 = *(const float2*)&Bp[(kg * 2 + 0) * 64 + lane * 2];
            float2 f1 = *(const float2*)&Bp[(kg * 2 + 1) * 64 + lane * 2];
            unsigned bq0[2] = { __float_as_uint(f0.x), __float_as_uint(f0.y) };
            unsigned bq1[2] = { __float_as_uint(f1.x), __float_as_uint(f1.y) };
#pragma unroll
            for (int mt = 0; mt < 4; mt++) {
                float4 av = __ldcg((const float4*)&hrbuf[((w * 4 + mt) * 16 + ks) * 128 + Abase]);
                unsigned af[4] = { __float_as_uint(av.x), __float_as_uint(av.y),
                                   __float_as_uint(av.z), __float_as_uint(av.w) };
                mma8(acc[mt][0], af, bq0);
                mma8(acc[mt][1], af, bq1);
            }
        }
        {
            float s[4];
            reduce16(red, acc, w, c, q, jj, b0, s);
            float xv[4] = { xh4.x, xh4.y, xh4.z, xh4.w };
#pragma unroll
            for (int i = 0; i < 4; i++) {
                float ht = tanhf(xv[i] + s[i]);
                hst[i] = zst[i] * hst[i] + (1.f - zst[i]) * ht;
            }
            // bf16x2 exchange: pair (jj, jj+1) via shfl, even-jj threads store
            unsigned* hb = g_hB[t & 1];
#pragma unroll
            for (int i = 0; i < 4; i++) {
                float ph = __shfl_xor_sync(0xffffffffu, hst[i], 16);
                if ((tid & 16) == 0)
                    __stcg(&hb[hb_base + i * 16], bf16pack(ph, hst[i]));
            }
            if (t == TT - 1) {
#pragma unroll
                for (int i = 0; i < 4; i++) g_hT[kj * BB + b0 + i] = hst[i];
            }
        }
        __syncthreads();
        if (tid == 0) publish(&g_fh[blockIdx.x], F0h + 1 + t);

        // ---------- phase 2: h @ Vz^T and h @ Vr^T  (bf16 k16) ----------
        wait8(g_fh, prodbase, F0h + 1 + t);
        const unsigned* hbc = g_hB[t & 1];

        float az[4][2][4], ar[4][2][4];
#pragma unroll
        for (int mt = 0; mt < 4; mt++)
#pragma unroll
            for (int nt = 0; nt < 2; nt++)
#pragma unroll
                for (int r = 0; r < 4; r++) { az[mt][nt][r] = 0.f; ar[mt][nt][r] = 0.f; }

#pragma unroll 4
        for (int kc8 = 0; kc8 < 8; kc8++) {
            int kcg = w * 8 + kc8;
            uint2 bz0 = *(const uint2*)&Bz16[((kcg * 2 + 0) * 32 + lane) * 2];
            uint2 bz1 = *(const uint2*)&Bz16[((kcg * 2 + 1) * 32 + lane) * 2];
            uint2 br0 = *(const uint2*)&Br16[((kcg * 2 + 0) * 32 + lane) * 2];
            uint2 br1 = *(const uint2*)&Br16[((kcg * 2 + 1) * 32 + lane) * 2];
            unsigned vz0[2] = { bz0.x, bz0.y }, vz1[2] = { bz1.x, bz1.y };
            unsigned vr0[2] = { br0.x, br0.y }, vr1[2] = { br1.x, br1.y };
#pragma unroll
            for (int mt = 0; mt < 4; mt++) {
                uint4 av = __ldcg((const uint4*)&hbc[((kcg * 4 + mt) * 32 + lane) * 4]);
                unsigned af[4] = { av.x, av.y, av.z, av.w };
                mma16(az[mt][0], af, vz0);
                mma16(az[mt][1], af, vz1);
                mma16(ar[mt][0], af, vr0);
                mma16(ar[mt][1], af, vr1);
            }
        }
        {
            float sz[4], sr[4];
            reduce16(red, az, w, c, q, jj, b0, sz);
            __syncthreads();
            reduce16(red, ar, w, c, q, jj, b0, sr);
            float zv[4] = { xz4.x, xz4.y, xz4.z, xz4.w };
            float rv[4] = { xr4.x, xr4.y, xr4.z, xr4.w };
            float* hrw = g_hrP[t & 1];
#pragma unroll
            for (int i = 0; i < 4; i++) {
                zst[i] = sigm_(zv[i] + sz[i]);
                float ri = sigm_(rv[i] + sr[i]);
                __stcg(&hrw[pbase + i * 16], __uint_as_float(cvt_tf32(hst[i] * ri)));
            }
        }
        __syncthreads();
        if (tid == 0) publish(&g_fhr[blockIdx.x], F0hr + 2 + t);
    }
}

// -------- kernel 3: output projection --------
__global__ __launch_bounds__(256) void out_kernel(
    const float* __restrict__ Wo, const float* __restrict__ bo, float* __restrict__ out)
{
    const int b = threadIdx.x & 63;
    const int o = blockIdx.x * 4 + (threadIdx.x >> 6);
    float s = 0.f;
#pragma unroll 8
    for (int j = 0; j < HH; j++)
        s += g_hT[j * BB + b] * Wo[o * HH + j];
    out[b * OUTD + o] = s + bo[o];
}

extern "C" void kernel_launch(void* const* d_in, const int* in_sizes, int n_in,
                              void* d_out, int out_size) {
    const float* X  = (const float*)d_in[0];
    const float* Wx = (const float*)d_in[1];
    const float* bx = (const float*)d_in[2];
    const float* Wh = (const float*)d_in[3];
    const float* Uz = (const float*)d_in[4];
    const float* bz = (const float*)d_in[5];
    const float* Vz = (const float*)d_in[6];
    const float* Ur = (const float*)d_in[7];
    const float* br = (const float*)d_in[8];
    const float* Vr = (const float*)d_in[9];
    const float* Wo = (const float*)d_in[10];
    const float* bo = (const float*)d_in[11];
    float* out = (float*)d_out;

    const int scan_smem = (32768 + 4 * 16 * RSTR) * (int)sizeof(float);
    cudaFuncSetAttribute(scan_kernel, cudaFuncAttributeMaxDynamicSharedMemorySize, scan_smem);

    dim3 pg(HH / 64, TT, 3);
    proj_kernel<<<pg, 256>>>(X, Wx, Uz, Ur, bx, bz, br);
    scan_kernel<<<NCTA, 256, scan_smem>>>(Wh, Vz, Vr);
    out_kernel<<<OUTD / 4, 256>>>(Wo, bo, out);
}